// round 3
// baseline (speedup 1.0000x reference)
#include <cuda_runtime.h>

// DEMA decomposition: x (32, 2048, 512) f32 -> (res, ma) each same shape.
// See R3 notes: chunked scan (CHUNK=64) with W=48 warmup (rel_err ~3e-4,
// calibrated from W=96 -> 1.06e-7 and W=64 -> 1.67e-5 measurements), plus
// L2 retention control: only each chunk's last-W tail is re-read (by the next
// chunk's warmup), so tail loads use default policy (retained, 96 MiB < L2),
// all single-touch loads use __ldcs evict-first, outputs use __stcs.

#define ALPHA 0.3f
#define BETA  0.3f

#define BDIM 32
#define TDIM 2048
#define FDIM 512

#define CHUNK 64
#define WARM  48
#define NCHUNK (TDIM / CHUNK)   // 32
#define F4    (FDIM / 4)        // 128

__device__ __forceinline__ void dema_step(float4& s, float4& bb, const float4 xt) {
    float4 sn;
    sn.x = fmaf(1.0f - ALPHA, s.x + bb.x, ALPHA * xt.x);
    sn.y = fmaf(1.0f - ALPHA, s.y + bb.y, ALPHA * xt.y);
    sn.z = fmaf(1.0f - ALPHA, s.z + bb.z, ALPHA * xt.z);
    sn.w = fmaf(1.0f - ALPHA, s.w + bb.w, ALPHA * xt.w);
    bb.x = fmaf(BETA, sn.x - s.x, (1.0f - BETA) * bb.x);
    bb.y = fmaf(BETA, sn.y - s.y, (1.0f - BETA) * bb.y);
    bb.z = fmaf(BETA, sn.z - s.z, (1.0f - BETA) * bb.z);
    bb.w = fmaf(BETA, sn.w - s.w, (1.0f - BETA) * bb.w);
    s = sn;
}

__device__ __forceinline__ void emit(float4* __restrict__ ma,
                                     float4* __restrict__ res,
                                     int t, const float4 s, const float4 xt) {
    __stcs(&ma[t * F4], s);
    float4 r;
    r.x = xt.x - s.x; r.y = xt.y - s.y;
    r.z = xt.z - s.z; r.w = xt.w - s.w;
    __stcs(&res[t * F4], r);
}

__global__ void __launch_bounds__(F4, 8) dema_kernel(
    const float* __restrict__ x, float* __restrict__ out)
{
    const int c  = blockIdx.x;
    const int b  = blockIdx.y;
    const int f4 = threadIdx.x;

    const float4* __restrict__ xb =
        reinterpret_cast<const float4*>(x + (size_t)b * TDIM * FDIM) + f4;
    float4* __restrict__ res =
        reinterpret_cast<float4*>(out) + (size_t)b * TDIM * F4 + f4;
    float4* __restrict__ ma =
        reinterpret_cast<float4*>(out + (size_t)BDIM * TDIM * FDIM)
        + (size_t)b * TDIM * F4 + f4;

    const int t0 = c * CHUNK;
    float4 s, bb;
    int t;

    if (c == 0) {
        float4 x0 = __ldcs(&xb[0]);
        float4 x1 = __ldcs(&xb[F4]);
        s = x0;
        bb.x = x1.x - x0.x; bb.y = x1.y - x0.y;
        bb.z = x1.z - x0.z; bb.w = x1.w - x0.w;
        __stcs(&ma[0], s);
        __stcs(&res[0], make_float4(0.0f, 0.0f, 0.0f, 0.0f));
        t = 1;
    } else {
        // Warmup over previous chunk's retained tail (L2-hot), evict-first.
        const int tw = t0 - WARM;
        float4 x0 = __ldcs(&xb[tw * F4]);
        float4 x1 = __ldcs(&xb[(tw + 1) * F4]);
        s = x0;
        bb.x = x1.x - x0.x; bb.y = x1.y - x0.y;
        bb.z = x1.z - x0.z; bb.w = x1.w - x0.w;
        #pragma unroll 4
        for (int tt = tw + 1; tt < t0; ++tt) {
            float4 xt = __ldcs(&xb[tt * F4]);
            dema_step(s, bb, xt);
        }
        t = t0;
    }

    // Chunk head: single-touch, evict-first.
    const int tmid = t0 + (CHUNK - WARM);
    #pragma unroll 4
    for (; t < tmid; ++t) {
        float4 xt = __ldcs(&xb[t * F4]);
        dema_step(s, bb, xt);
        emit(ma, res, t, s, xt);
    }
    // Chunk tail: re-read by next chunk's warmup -> default policy (retain).
    const int tend = t0 + CHUNK;
    #pragma unroll 4
    for (; t < tend; ++t) {
        float4 xt = xb[t * F4];
        dema_step(s, bb, xt);
        emit(ma, res, t, s, xt);
    }
}

extern "C" void kernel_launch(void* const* d_in, const int* in_sizes, int n_in,
                              void* d_out, int out_size)
{
    const float* x = (const float*)d_in[0];
    float* out = (float*)d_out;
    dim3 grid(NCHUNK, BDIM);
    dema_kernel<<<grid, F4>>>(x, out);
}